// round 1
// baseline (speedup 1.0000x reference)
#include <cuda_runtime.h>

#define N_TOK 343
#define HEADS 8
#define HD    32
#define DIM   256
#define BWIN  256
#define NN    (N_TOK * N_TOK)     /* 117649 */
#define KSTR  36                  /* K smem row stride (floats): 36/4=9 odd -> conflict-free f4 */
#define VSTR  348                 /* V^T smem row stride: 348/4=87 odd -> conflict-free f4 */
#define NP4   344                 /* padded j extent (mult of 4 >= 343) */
#define QSCALE 0.17677669529663689f

// ---------------- scratch (device globals; no allocation allowed) -------------
__device__ float g_q[BWIN * HEADS * N_TOK * HD];
__device__ float g_k[BWIN * HEADS * N_TOK * HD];
__device__ float g_v[BWIN * HEADS * N_TOK * HD];
__device__ float g_attn[BWIN * N_TOK * DIM];
__device__ float g_bias2[HEADS * NN];

// ---------------- kernel 0: fold rpb_table gather into dense bias ------------
__global__ void wa3d_bias_kernel(const float* __restrict__ table,
                                 const int* __restrict__ rel) {
    int idx = blockIdx.x * blockDim.x + threadIdx.x;
    if (idx < NN) {
        int r = rel[idx];
        #pragma unroll
        for (int h = 0; h < HEADS; h++)
            g_bias2[h * NN + idx] = table[r * HEADS + h];
    }
}

// ---------------- kernel 1: QKV GEMM (87808x768x256) + scatter ----------------
// BM=128, BN=128, BK=8, 256 threads, 8x8 per thread. All dims divide evenly.
__global__ __launch_bounds__(256) void wa3d_qkv_gemm(const float* __restrict__ A,
                                                     const float* __restrict__ W,
                                                     const float* __restrict__ bias) {
    __shared__ float As[8][128];
    __shared__ float Bs[8][128];
    const int LDA = 256, LDW = 768;
    int tid = threadIdx.x;
    int bm = blockIdx.x, bn = blockIdx.y;
    int ty = tid >> 4, tx = tid & 15;
    int arow = tid >> 1, acol = (tid & 1) * 4;
    int brow = tid >> 5, bcol = (tid & 31) * 4;
    const float* Ap = A + (bm * 128 + arow) * LDA + acol;
    const float* Wp = W + brow * LDW + bn * 128 + bcol;

    float acc[8][8];
    #pragma unroll
    for (int i = 0; i < 8; i++)
        #pragma unroll
        for (int j = 0; j < 8; j++) acc[i][j] = 0.f;

    for (int k0 = 0; k0 < 256; k0 += 8) {
        float4 av = *(const float4*)(Ap + k0);
        float4 bv = *(const float4*)(Wp + k0 * LDW);
        __syncthreads();
        As[acol + 0][arow] = av.x;
        As[acol + 1][arow] = av.y;
        As[acol + 2][arow] = av.z;
        As[acol + 3][arow] = av.w;
        *(float4*)&Bs[brow][bcol] = bv;
        __syncthreads();
        #pragma unroll
        for (int kk = 0; kk < 8; kk++) {
            float4 a0 = *(float4*)&As[kk][ty * 4];
            float4 a1 = *(float4*)&As[kk][ty * 4 + 64];
            float4 b0 = *(float4*)&Bs[kk][tx * 4];
            float4 b1 = *(float4*)&Bs[kk][tx * 4 + 64];
            float af[8] = {a0.x, a0.y, a0.z, a0.w, a1.x, a1.y, a1.z, a1.w};
            float bf[8] = {b0.x, b0.y, b0.z, b0.w, b1.x, b1.y, b1.z, b1.w};
            #pragma unroll
            for (int i = 0; i < 8; i++)
                #pragma unroll
                for (int j = 0; j < 8; j++) acc[i][j] += af[i] * bf[j];
        }
    }
    #pragma unroll
    for (int i = 0; i < 8; i++) {
        int gr = bm * 128 + ((i < 4) ? ty * 4 + i : 64 + ty * 4 + (i - 4));
        int b = gr / N_TOK, n = gr % N_TOK;
        #pragma unroll
        for (int j = 0; j < 8; j++) {
            int gc = bn * 128 + ((j < 4) ? tx * 4 + j : 64 + tx * 4 + (j - 4));
            float val = acc[i][j] + bias[gc];
            int s = gc >> 8;
            int h = (gc >> 5) & 7;
            int d = gc & 31;
            float* dst = (s == 0) ? g_q : (s == 1) ? g_k : g_v;
            if (s == 0) val *= QSCALE;
            dst[((b * HEADS + h) * N_TOK + n) * HD + d] = val;
        }
    }
}

// ---------------- kernel 3: proj GEMM (87808x256x256) + bias ------------------
__global__ __launch_bounds__(256) void wa3d_proj_gemm(const float* __restrict__ W,
                                                      const float* __restrict__ bias,
                                                      float* __restrict__ out) {
    __shared__ float As[8][128];
    __shared__ float Bs[8][128];
    const int LDA = 256, LDW = 256;
    const float* A = g_attn;
    int tid = threadIdx.x;
    int bm = blockIdx.x, bn = blockIdx.y;
    int ty = tid >> 4, tx = tid & 15;
    int arow = tid >> 1, acol = (tid & 1) * 4;
    int brow = tid >> 5, bcol = (tid & 31) * 4;
    const float* Ap = A + (bm * 128 + arow) * LDA + acol;
    const float* Wp = W + brow * LDW + bn * 128 + bcol;

    float acc[8][8];
    #pragma unroll
    for (int i = 0; i < 8; i++)
        #pragma unroll
        for (int j = 0; j < 8; j++) acc[i][j] = 0.f;

    for (int k0 = 0; k0 < 256; k0 += 8) {
        float4 av = *(const float4*)(Ap + k0);
        float4 bv = *(const float4*)(Wp + k0 * LDW);
        __syncthreads();
        As[acol + 0][arow] = av.x;
        As[acol + 1][arow] = av.y;
        As[acol + 2][arow] = av.z;
        As[acol + 3][arow] = av.w;
        *(float4*)&Bs[brow][bcol] = bv;
        __syncthreads();
        #pragma unroll
        for (int kk = 0; kk < 8; kk++) {
            float4 a0 = *(float4*)&As[kk][ty * 4];
            float4 a1 = *(float4*)&As[kk][ty * 4 + 64];
            float4 b0 = *(float4*)&Bs[kk][tx * 4];
            float4 b1 = *(float4*)&Bs[kk][tx * 4 + 64];
            float af[8] = {a0.x, a0.y, a0.z, a0.w, a1.x, a1.y, a1.z, a1.w};
            float bf[8] = {b0.x, b0.y, b0.z, b0.w, b1.x, b1.y, b1.z, b1.w};
            #pragma unroll
            for (int i = 0; i < 8; i++)
                #pragma unroll
                for (int j = 0; j < 8; j++) acc[i][j] += af[i] * bf[j];
        }
    }
    #pragma unroll
    for (int i = 0; i < 8; i++) {
        int gr = bm * 128 + ((i < 4) ? ty * 4 + i : 64 + ty * 4 + (i - 4));
        #pragma unroll
        for (int j = 0; j < 8; j++) {
            int gc = bn * 128 + ((j < 4) ? tx * 4 + j : 64 + tx * 4 + (j - 4));
            out[gr * DIM + gc] = acc[i][j] + bias[gc];
        }
    }
}

// ---------------- kernel 2: fused attention, one CTA per (window, head) -------
// smem: K[352][36] + V^T[32][348] + P[8 warps][4][344] + Q[8][4][32] = 143360 B
#define ATTN_SMEM ((352 * KSTR + 32 * VSTR + 8 * 4 * NP4 + 8 * 128) * 4)

__global__ __launch_bounds__(256) void wa3d_attn_kernel(const float* __restrict__ mask) {
    extern __shared__ float sm[];
    float* ks  = sm;                         // 352*36
    float* vsT = sm + 352 * KSTR;            // 32*348
    float* ps  = vsT + 32 * VSTR;            // 8*4*344
    float* qs  = ps + 8 * 4 * NP4;           // 8*128

    int bx = blockIdx.x;
    int h = bx & 7, b = bx >> 3;
    int tid = threadIdx.x, warp = tid >> 5, lane = tid & 31;
    int base = (b * HEADS + h) * (N_TOK * HD);
    const float* kb = g_k + base;
    const float* vb = g_v + base;
    const float* qb = g_q + base;
    const float* bb = g_bias2 + h * NN;
    const float* mb = mask + (b & 63) * NN;
    float* ob = g_attn + b * (N_TOK * DIM) + h * HD;

    // stage K (row-major, stride 36, zero-padded rows 343..351)
    for (int idx = tid; idx < 352 * 32; idx += 256) {
        int r = idx >> 5, d = idx & 31;
        ks[r * KSTR + d] = (r < N_TOK) ? kb[r * HD + d] : 0.f;
    }
    // stage V transposed (stride 348, zero-padded cols 343..347)
    for (int idx = tid; idx < 348 * 32; idx += 256) {
        int r = idx >> 5, d = idx & 31;
        vsT[d * VSTR + r] = (r < N_TOK) ? vb[r * HD + d] : 0.f;
    }
    __syncthreads();

    float* psw = ps + warp * 4 * NP4;
    float* qsw = qs + warp * 128;

    for (int t = warp; t < 86; t += 8) {
        int i0 = t * 4;
        #pragma unroll
        for (int r = 0; r < 4; r++) {
            int i = i0 + r;
            qsw[r * 32 + lane] = (i < N_TOK) ? qb[i * HD + lane] : 0.f;
        }
        __syncwarp();

        float acc[4][11];
        #pragma unroll
        for (int r = 0; r < 4; r++)
            #pragma unroll
            for (int c = 0; c < 11; c++) acc[r][c] = 0.f;

        // S = Q K^T   (lane owns j = c*32+lane; 4 rows per warp)
        #pragma unroll
        for (int d4 = 0; d4 < 32; d4 += 4) {
            float4 q0 = *(float4*)&qsw[0 * 32 + d4];
            float4 q1 = *(float4*)&qsw[1 * 32 + d4];
            float4 q2 = *(float4*)&qsw[2 * 32 + d4];
            float4 q3 = *(float4*)&qsw[3 * 32 + d4];
            #pragma unroll
            for (int c = 0; c < 11; c++) {
                float4 kv = *(float4*)&ks[(c * 32 + lane) * KSTR + d4];
                acc[0][c] += q0.x * kv.x + q0.y * kv.y + q0.z * kv.z + q0.w * kv.w;
                acc[1][c] += q1.x * kv.x + q1.y * kv.y + q1.z * kv.z + q1.w * kv.w;
                acc[2][c] += q2.x * kv.x + q2.y * kv.y + q2.z * kv.z + q2.w * kv.w;
                acc[3][c] += q3.x * kv.x + q3.y * kv.y + q3.z * kv.z + q3.w * kv.w;
            }
        }

        // + bias + mask, track row max
        float mx[4] = {-1e30f, -1e30f, -1e30f, -1e30f};
        #pragma unroll
        for (int c = 0; c < 11; c++) {
            int j = c * 32 + lane;
            bool jv = (j < N_TOK);
            #pragma unroll
            for (int r = 0; r < 4; r++) {
                int i = i0 + r;
                float val;
                if (jv && i < N_TOK)
                    val = acc[r][c] + bb[i * N_TOK + j] + mb[i * N_TOK + j];
                else
                    val = -1e30f;
                acc[r][c] = val;
                mx[r] = fmaxf(mx[r], val);
            }
        }

        // softmax per row, write P to smem
        #pragma unroll
        for (int r = 0; r < 4; r++) {
            float m = mx[r];
            #pragma unroll
            for (int off = 16; off; off >>= 1)
                m = fmaxf(m, __shfl_xor_sync(0xffffffffu, m, off));
            float s = 0.f;
            #pragma unroll
            for (int c = 0; c < 11; c++) {
                float e = __expf(acc[r][c] - m);
                acc[r][c] = e;
                s += e;
            }
            #pragma unroll
            for (int off = 16; off; off >>= 1)
                s += __shfl_xor_sync(0xffffffffu, s, off);
            float inv = 1.f / s;
            #pragma unroll
            for (int c = 0; c < 11; c++) {
                int j = c * 32 + lane;
                if (j < NP4) psw[r * NP4 + j] = acc[r][c] * inv;
            }
        }
        __syncwarp();

        // O = P V   (lane owns output dim d = lane)
        float o0 = 0.f, o1 = 0.f, o2 = 0.f, o3 = 0.f;
        const float* vrow = &vsT[lane * VSTR];
        #pragma unroll 2
        for (int j4 = 0; j4 < NP4; j4 += 4) {
            float4 vv = *(const float4*)&vrow[j4];
            float4 p0 = *(float4*)&psw[0 * NP4 + j4];
            float4 p1 = *(float4*)&psw[1 * NP4 + j4];
            float4 p2 = *(float4*)&psw[2 * NP4 + j4];
            float4 p3 = *(float4*)&psw[3 * NP4 + j4];
            o0 += p0.x * vv.x + p0.y * vv.y + p0.z * vv.z + p0.w * vv.w;
            o1 += p1.x * vv.x + p1.y * vv.y + p1.z * vv.z + p1.w * vv.w;
            o2 += p2.x * vv.x + p2.y * vv.y + p2.z * vv.z + p2.w * vv.w;
            o3 += p3.x * vv.x + p3.y * vv.y + p3.z * vv.z + p3.w * vv.w;
        }
        if (i0 + 0 < N_TOK) ob[(i0 + 0) * DIM + lane] = o0;
        if (i0 + 1 < N_TOK) ob[(i0 + 1) * DIM + lane] = o1;
        if (i0 + 2 < N_TOK) ob[(i0 + 2) * DIM + lane] = o2;
        if (i0 + 3 < N_TOK) ob[(i0 + 3) * DIM + lane] = o3;
    }
}

// ------------------------------ launch ----------------------------------------
extern "C" void kernel_launch(void* const* d_in, const int* in_sizes, int n_in,
                              void* d_out, int out_size) {
    const float* x      = (const float*)d_in[0];
    const float* mask   = (const float*)d_in[1];
    const float* qkv_w  = (const float*)d_in[2];
    const float* qkv_b  = (const float*)d_in[3];
    const float* proj_w = (const float*)d_in[4];
    const float* proj_b = (const float*)d_in[5];
    const float* rpb    = (const float*)d_in[6];
    const int*   rel    = (const int*)d_in[7];
    float* out = (float*)d_out;

    cudaFuncSetAttribute(wa3d_attn_kernel,
                         cudaFuncAttributeMaxDynamicSharedMemorySize, ATTN_SMEM);

    wa3d_bias_kernel<<<(NN + 255) / 256, 256>>>(rpb, rel);
    wa3d_qkv_gemm<<<dim3(87808 / 128, 768 / 128), 256>>>(x, qkv_w, qkv_b);
    wa3d_attn_kernel<<<BWIN * HEADS, 256, ATTN_SMEM>>>(mask);
    wa3d_proj_gemm<<<dim3(87808 / 128, 256 / 128), 256>>>(proj_w, proj_b, out);
}

// round 4
// speedup vs baseline: 2.0060x; 2.0060x over previous
#include <cuda_runtime.h>
#include <cstdint>

#define N_TOK 343
#define HEADS 8
#define HD    32
#define DIM   256
#define BWIN  256
#define NN    (N_TOK * N_TOK)     /* 117649 */
#define ROWS_TOT 87808            /* BWIN * N_TOK */
#define QSCALE 0.17677669529663689f

// ---------------- scratch (device globals; no allocation allowed) -------------
__device__ float g_q[BWIN * HEADS * N_TOK * HD];
__device__ float g_k[BWIN * HEADS * N_TOK * HD];
__device__ float g_v[BWIN * HEADS * N_TOK * HD];
__device__ float g_attn[BWIN * N_TOK * DIM];
__device__ float g_bias2[HEADS * NN];

// ---------------- tf32 helpers ------------------------------------------------
__device__ __forceinline__ uint32_t f2tf(float x) {
    uint32_t u;
    asm("cvt.rna.tf32.f32 %0, %1;" : "=r"(u) : "f"(x));
    return u;
}

__device__ __forceinline__ void mma8(float c[4],
                                     uint32_t a0, uint32_t a1, uint32_t a2, uint32_t a3,
                                     uint32_t b0, uint32_t b1) {
    asm volatile(
        "mma.sync.aligned.m16n8k8.row.col.f32.tf32.tf32.f32 "
        "{%0,%1,%2,%3},{%4,%5,%6,%7},{%8,%9},{%0,%1,%2,%3};"
        : "+f"(c[0]), "+f"(c[1]), "+f"(c[2]), "+f"(c[3])
        : "r"(a0), "r"(a1), "r"(a2), "r"(a3), "r"(b0), "r"(b1));
}

// ---------------- kernel 0: fold rpb_table gather into dense bias ------------
__global__ void wa3d_bias_kernel(const float* __restrict__ table,
                                 const int* __restrict__ rel) {
    int idx = blockIdx.x * blockDim.x + threadIdx.x;
    if (idx < NN) {
        int r = rel[idx];
        #pragma unroll
        for (int h = 0; h < HEADS; h++)
            g_bias2[h * NN + idx] = table[r * HEADS + h];
    }
}

// ---------------- tf32 mma GEMM: C(128x128) per CTA, BK=16 -------------------
// MODE 0: A = Aparam (x), epilogue scatters into g_q/g_k/g_v with q-scale.
// MODE 1: A = g_attn (device symbol referenced in device code), C+bias out.
template<int LDW, int MODE>
__global__ __launch_bounds__(256, 2) void wa3d_gemm(const float* __restrict__ Aparam,
                                                    const float* __restrict__ W,
                                                    const float* __restrict__ bias,
                                                    float* __restrict__ out) {
    __shared__ uint32_t As[2][128 * 20];
    __shared__ uint32_t Bs[2][16 * 132];

    int tid = threadIdx.x;
    int w = tid >> 5, lane = tid & 31, g = lane >> 2, t = lane & 3;
    int wm = (w & 3) * 32, wn = (w >> 2) * 64;
    int bm = blockIdx.x, bn = blockIdx.y;
    const float* Asrc = (MODE == 0) ? Aparam : (const float*)g_attn;
    const float* Ab = Asrc + (long)bm * 128 * 256;
    const float* Wb = W + bn * 128;

    float acc[2][8][4];
    #pragma unroll
    for (int mf = 0; mf < 2; mf++)
        #pragma unroll
        for (int nf = 0; nf < 8; nf++)
            #pragma unroll
            for (int e = 0; e < 4; e++) acc[mf][nf][e] = 0.f;

    float4 pa[2], pb[2];
    #pragma unroll
    for (int i = 0; i < 2; i++) {
        int id = tid + 256 * i;
        pa[i] = *(const float4*)(Ab + (id >> 2) * 256 + (id & 3) * 4);
        pb[i] = *(const float4*)(Wb + (long)(id >> 5) * LDW + (id & 31) * 4);
    }
    #pragma unroll
    for (int i = 0; i < 2; i++) {
        int id = tid + 256 * i;
        uint4 va = {f2tf(pa[i].x), f2tf(pa[i].y), f2tf(pa[i].z), f2tf(pa[i].w)};
        *(uint4*)&As[0][(id >> 2) * 20 + (id & 3) * 4] = va;
        uint4 vb = {f2tf(pb[i].x), f2tf(pb[i].y), f2tf(pb[i].z), f2tf(pb[i].w)};
        *(uint4*)&Bs[0][(id >> 5) * 132 + (id & 31) * 4] = vb;
    }
    __syncthreads();

    for (int s = 0; s < 16; s++) {
        int buf = s & 1;
        if (s < 15) {
            int k0 = (s + 1) * 16;
            #pragma unroll
            for (int i = 0; i < 2; i++) {
                int id = tid + 256 * i;
                pa[i] = *(const float4*)(Ab + (id >> 2) * 256 + k0 + (id & 3) * 4);
                pb[i] = *(const float4*)(Wb + (long)(k0 + (id >> 5)) * LDW + (id & 31) * 4);
            }
        }
        const uint32_t* Asb = As[buf];
        const uint32_t* Bsb = Bs[buf];
        #pragma unroll
        for (int kk = 0; kk < 2; kk++) {
            int k = kk * 8;
            uint32_t afr[2][4];
            #pragma unroll
            for (int mf = 0; mf < 2; mf++) {
                const uint32_t* ap = Asb + (wm + mf * 16 + g) * 20 + k + t;
                afr[mf][0] = ap[0];
                afr[mf][1] = ap[8 * 20];
                afr[mf][2] = ap[4];
                afr[mf][3] = ap[8 * 20 + 4];
            }
            #pragma unroll
            for (int nf = 0; nf < 8; nf++) {
                const uint32_t* bp = Bsb + (k + t) * 132 + wn + nf * 8 + g;
                uint32_t b0 = bp[0], b1 = bp[4 * 132];
                mma8(acc[0][nf], afr[0][0], afr[0][1], afr[0][2], afr[0][3], b0, b1);
                mma8(acc[1][nf], afr[1][0], afr[1][1], afr[1][2], afr[1][3], b0, b1);
            }
        }
        if (s < 15) {
            int nb = (s + 1) & 1;
            #pragma unroll
            for (int i = 0; i < 2; i++) {
                int id = tid + 256 * i;
                uint4 va = {f2tf(pa[i].x), f2tf(pa[i].y), f2tf(pa[i].z), f2tf(pa[i].w)};
                *(uint4*)&As[nb][(id >> 2) * 20 + (id & 3) * 4] = va;
                uint4 vb = {f2tf(pb[i].x), f2tf(pb[i].y), f2tf(pb[i].z), f2tf(pb[i].w)};
                *(uint4*)&Bs[nb][(id >> 5) * 132 + (id & 31) * 4] = vb;
            }
        }
        __syncthreads();
    }

    // ----- epilogue -----
    if (MODE == 0) {
        #pragma unroll
        for (int mf = 0; mf < 2; mf++) {
            #pragma unroll
            for (int half = 0; half < 2; half++) {
                int row = bm * 128 + wm + mf * 16 + g + half * 8;
                int bwin = row / N_TOK, n = row - bwin * N_TOK;
                #pragma unroll
                for (int nf = 0; nf < 8; nf++) {
                    #pragma unroll
                    for (int e2 = 0; e2 < 2; e2++) {
                        int c = bn * 128 + wn + nf * 8 + 2 * t + e2;
                        float v = acc[mf][nf][half * 2 + e2] + bias[c];
                        int sct = c >> 8;
                        int hh = (c >> 5) & 7;
                        int d = c & 31;
                        float* dst = (sct == 0) ? g_q : (sct == 1) ? g_k : g_v;
                        if (sct == 0) v *= QSCALE;
                        dst[((bwin * HEADS + hh) * N_TOK + n) * HD + d] = v;
                    }
                }
            }
        }
    } else {
        #pragma unroll
        for (int mf = 0; mf < 2; mf++) {
            #pragma unroll
            for (int half = 0; half < 2; half++) {
                int row = bm * 128 + wm + mf * 16 + g + half * 8;
                #pragma unroll
                for (int nf = 0; nf < 8; nf++) {
                    int c = bn * 128 + wn + nf * 8 + 2 * t;
                    float2 st;
                    st.x = acc[mf][nf][half * 2 + 0] + bias[c];
                    st.y = acc[mf][nf][half * 2 + 1] + bias[c + 1];
                    *(float2*)&out[(long)row * 256 + c] = st;
                }
            }
        }
    }
}

// ---------------- attention: tf32 mma flash-style, one CTA per (b,h) ---------
#define ATTN_SMEM_U32 (352 * 36 + 352 * 40 + 64 * 36 + 64 + 64 + 128)
#define ATTN_SMEM (ATTN_SMEM_U32 * 4)

__global__ __launch_bounds__(256, 1) void wa3d_attn_kernel(const float* __restrict__ mask) {
    extern __shared__ uint32_t smu[];
    uint32_t* ks = smu;                       // 352*36
    uint32_t* vs = ks + 352 * 36;             // 352*40
    uint32_t* qs = vs + 352 * 40;             // 64*36  (>= 2048 scratch floats)
    float* sm_m = (float*)(qs + 64 * 36);     // 128
    float* sm_s = sm_m + 128;                 // 128

    int bx = blockIdx.x;
    int h = bx & 7, b = bx >> 3;
    int tid = threadIdx.x, w = tid >> 5, lane = tid & 31;
    int g = lane >> 2, t = lane & 3;
    long base = (long)(b * HEADS + h) * (N_TOK * HD);
    const float* kb = g_k + base;
    const float* vb = g_v + base;
    const float* qb = g_q + base;
    const float* bb = g_bias2 + (long)h * NN;
    const float* mb = mask + (long)(b & 63) * NN;
    float* ob = g_attn + (long)b * (N_TOK * DIM) + h * HD;

    // stage K (tf32, stride 36) and V (tf32, stride 40), zero-padded
    for (int idx = tid; idx < 352 * 32; idx += 256) {
        int r = idx >> 5, d = idx & 31;
        float kv = (r < N_TOK) ? kb[r * HD + d] : 0.f;
        float vv = (r < N_TOK) ? vb[r * HD + d] : 0.f;
        ks[r * 36 + d] = f2tf(kv);
        vs[r * 40 + d] = f2tf(vv);
    }
    __syncthreads();

    int mi = (w & 3) * 16;         // row tile within strip
    int jhi = w >> 2;              // j-half index (0/1)
    int jh = jhi * 176;            // j-col base
    float* scratch = (float*)qs;
    int srcA = (lane & 28) | (t >> 1);

    for (int is = 0; is < 6; is++) {
        int i0 = is * 64;
        // stage Q strip (64 rows, tf32, stride 36)
        for (int idx = tid; idx < 64 * 32; idx += 256) {
            int r = idx >> 5, d = idx & 31;
            int i = i0 + r;
            float qv = (i < N_TOK) ? qb[i * HD + d] : 0.f;
            qs[r * 36 + d] = f2tf(qv);
        }
        __syncthreads();

        // ---- S = Q K^T over this warp's 16 rows x 176 cols ----
        float sacc[22][4];
        #pragma unroll
        for (int nf = 0; nf < 22; nf++)
            #pragma unroll
            for (int e = 0; e < 4; e++) sacc[nf][e] = 0.f;

        #pragma unroll
        for (int kk = 0; kk < 4; kk++) {
            int k = kk * 8;
            const uint32_t* ap = qs + (mi + g) * 36 + k + t;
            uint32_t a0 = ap[0], a1 = ap[8 * 36], a2 = ap[4], a3 = ap[8 * 36 + 4];
            #pragma unroll
            for (int nf = 0; nf < 22; nf++) {
                const uint32_t* bp = ks + (jh + nf * 8 + g) * 36 + k + t;
                mma8(sacc[nf], a0, a1, a2, a3, bp[0], bp[4]);  // b1: k+4 (dim axis!)
            }
        }

        // ---- + bias + mask (in registers) ----
        int i_lo = i0 + mi + g;
        int i_hi = i_lo + 8;
        bool rlo = i_lo < N_TOK, rhi = i_hi < N_TOK;
        const float* bb0 = bb + (long)i_lo * N_TOK;
        const float* mb0 = mb + (long)i_lo * N_TOK;
        const float* bb1 = bb + (long)i_hi * N_TOK;
        const float* mb1 = mb + (long)i_hi * N_TOK;
        #pragma unroll
        for (int nf = 0; nf < 22; nf++) {
            int j0 = jh + nf * 8 + 2 * t;
            int j1 = j0 + 1;
            bool j0v = j0 < N_TOK, j1v = j1 < N_TOK;
            sacc[nf][0] = (rlo && j0v) ? sacc[nf][0] + bb0[j0] + mb0[j0] : -1e30f;
            sacc[nf][1] = (rlo && j1v) ? sacc[nf][1] + bb0[j1] + mb0[j1] : -1e30f;
            sacc[nf][2] = (rhi && j0v) ? sacc[nf][2] + bb1[j0] + mb1[j0] : -1e30f;
            sacc[nf][3] = (rhi && j1v) ? sacc[nf][3] + bb1[j1] + mb1[j1] : -1e30f;
        }

        // ---- softmax (registers + cross-warp pair exchange) ----
        float mlo = -1e30f, mhi = -1e30f;
        #pragma unroll
        for (int nf = 0; nf < 22; nf++) {
            mlo = fmaxf(mlo, fmaxf(sacc[nf][0], sacc[nf][1]));
            mhi = fmaxf(mhi, fmaxf(sacc[nf][2], sacc[nf][3]));
        }
        #pragma unroll
        for (int off = 1; off <= 2; off <<= 1) {
            mlo = fmaxf(mlo, __shfl_xor_sync(0xffffffffu, mlo, off));
            mhi = fmaxf(mhi, __shfl_xor_sync(0xffffffffu, mhi, off));
        }
        if (t == 0) {
            sm_m[jhi * 64 + mi + g] = mlo;
            sm_m[jhi * 64 + mi + 8 + g] = mhi;
        }
        __syncthreads();
        mlo = fmaxf(mlo, sm_m[(jhi ^ 1) * 64 + mi + g]);
        mhi = fmaxf(mhi, sm_m[(jhi ^ 1) * 64 + mi + 8 + g]);

        float slo = 0.f, shi = 0.f;
        #pragma unroll
        for (int nf = 0; nf < 22; nf++) {
            float e0 = __expf(sacc[nf][0] - mlo);
            float e1 = __expf(sacc[nf][1] - mlo);
            float e2 = __expf(sacc[nf][2] - mhi);
            float e3 = __expf(sacc[nf][3] - mhi);
            sacc[nf][0] = e0; sacc[nf][1] = e1; sacc[nf][2] = e2; sacc[nf][3] = e3;
            slo += e0 + e1;
            shi += e2 + e3;
        }
        #pragma unroll
        for (int off = 1; off <= 2; off <<= 1) {
            slo += __shfl_xor_sync(0xffffffffu, slo, off);
            shi += __shfl_xor_sync(0xffffffffu, shi, off);
        }
        if (t == 0) {
            sm_s[jhi * 64 + mi + g] = slo;
            sm_s[jhi * 64 + mi + 8 + g] = shi;
        }
        __syncthreads();
        slo += sm_s[(jhi ^ 1) * 64 + mi + g];
        shi += sm_s[(jhi ^ 1) * 64 + mi + 8 + g];
        float invlo = 1.f / slo, invhi = 1.f / shi;

        // ---- PV: permute S c-frags -> a-frags via shfl, mma against V ----
        float oacc[4][4];
        #pragma unroll
        for (int nv = 0; nv < 4; nv++)
            #pragma unroll
            for (int e = 0; e < 4; e++) oacc[nv][e] = 0.f;

        #pragma unroll
        for (int nf = 0; nf < 22; nf++) {
            int k = jh + nf * 8;
            uint32_t e0 = f2tf(sacc[nf][0]);
            uint32_t e1 = f2tf(sacc[nf][1]);
            uint32_t e2 = f2tf(sacc[nf][2]);
            uint32_t e3 = f2tf(sacc[nf][3]);
            uint32_t x0 = __shfl_sync(0xffffffffu, e0, srcA);
            uint32_t x1 = __shfl_sync(0xffffffffu, e1, srcA);
            uint32_t a0 = (t & 1) ? x1 : x0;
            uint32_t y0 = __shfl_sync(0xffffffffu, e0, srcA + 2);
            uint32_t y1 = __shfl_sync(0xffffffffu, e1, srcA + 2);
            uint32_t a2 = (t & 1) ? y1 : y0;
            x0 = __shfl_sync(0xffffffffu, e2, srcA);
            x1 = __shfl_sync(0xffffffffu, e3, srcA);
            uint32_t a1 = (t & 1) ? x1 : x0;
            y0 = __shfl_sync(0xffffffffu, e2, srcA + 2);
            y1 = __shfl_sync(0xffffffffu, e3, srcA + 2);
            uint32_t a3 = (t & 1) ? y1 : y0;
            const uint32_t* vp = vs + (k + t) * 40 + g;
            #pragma unroll
            for (int nv = 0; nv < 4; nv++)
                mma8(oacc[nv], a0, a1, a2, a3, vp[nv * 8], vp[4 * 40 + nv * 8]);
        }

        // ---- reduce across j-halves, scale by 1/sum, write out ----
        if (w >= 4) {
            float* sc = scratch + (w - 4) * 512;
            #pragma unroll
            for (int nv = 0; nv < 4; nv++)
                #pragma unroll
                for (int e = 0; e < 4; e++)
                    sc[(nv * 4 + e) * 32 + lane] = oacc[nv][e];
        }
        __syncthreads();
        if (w < 4) {
            float* sc = scratch + w * 512;
            #pragma unroll
            for (int nv = 0; nv < 4; nv++)
                #pragma unroll
                for (int e = 0; e < 4; e++)
                    oacc[nv][e] += sc[(nv * 4 + e) * 32 + lane];
            int ir0 = i0 + mi + g;
            int ir1 = ir0 + 8;
            #pragma unroll
            for (int nv = 0; nv < 4; nv++) {
                int col = nv * 8 + 2 * t;
                if (ir0 < N_TOK) {
                    float2 v;
                    v.x = oacc[nv][0] * invlo;
                    v.y = oacc[nv][1] * invlo;
                    *(float2*)&ob[(long)ir0 * DIM + col] = v;
                }
                if (ir1 < N_TOK) {
                    float2 v;
                    v.x = oacc[nv][2] * invhi;
                    v.y = oacc[nv][3] * invhi;
                    *(float2*)&ob[(long)ir1 * DIM + col] = v;
                }
            }
        }
        __syncthreads();   // protect qs (scratch) + sm arrays before next strip
    }
}

// ------------------------------ launch ----------------------------------------
extern "C" void kernel_launch(void* const* d_in, const int* in_sizes, int n_in,
                              void* d_out, int out_size) {
    const float* x      = (const float*)d_in[0];
    const float* mask   = (const float*)d_in[1];
    const float* qkv_w  = (const float*)d_in[2];
    const float* qkv_b  = (const float*)d_in[3];
    const float* proj_w = (const float*)d_in[4];
    const float* proj_b = (const float*)d_in[5];
    const float* rpb    = (const float*)d_in[6];
    const int*   rel    = (const int*)d_in[7];
    float* out = (float*)d_out;

    cudaFuncSetAttribute(wa3d_attn_kernel,
                         cudaFuncAttributeMaxDynamicSharedMemorySize, ATTN_SMEM);

    wa3d_bias_kernel<<<(NN + 255) / 256, 256>>>(rpb, rel);
    wa3d_gemm<768, 0><<<dim3(ROWS_TOT / 128, 6), 256>>>(x, qkv_w, qkv_b, nullptr);
    wa3d_attn_kernel<<<BWIN * HEADS, 256, ATTN_SMEM>>>(mask);
    wa3d_gemm<256, 1><<<dim3(ROWS_TOT / 128, 2), 256>>>(nullptr, proj_w, proj_b, out);
}

// round 5
// speedup vs baseline: 2.0097x; 1.0018x over previous
#include <cuda_runtime.h>
#include <cstdint>

#define N_TOK 343
#define HEADS 8
#define HD    32
#define DIM   256
#define BWIN  256
#define NN    (N_TOK * N_TOK)     /* 117649 */
#define ROWS_TOT 87808            /* BWIN * N_TOK */
#define CSTR  344                 /* combined bias+mask row stride (even -> f2 aligned) */
#define QSCALE 0.17677669529663689f

// ---------------- scratch (device globals; no allocation allowed) -------------
__device__ float g_q[BWIN * HEADS * N_TOK * HD];
__device__ float g_k[BWIN * HEADS * N_TOK * HD];
__device__ float g_v[BWIN * HEADS * N_TOK * HD];
__device__ float g_attn[BWIN * N_TOK * DIM];
__device__ float g_comb[64 * HEADS * N_TOK * CSTR];   /* 241.7 MB */

// ---------------- tf32 helpers ------------------------------------------------
__device__ __forceinline__ uint32_t f2tf(float x) {
    uint32_t u;
    asm("cvt.rna.tf32.f32 %0, %1;" : "=r"(u) : "f"(x));
    return u;
}

__device__ __forceinline__ void mma8(float c[4],
                                     uint32_t a0, uint32_t a1, uint32_t a2, uint32_t a3,
                                     uint32_t b0, uint32_t b1) {
    asm volatile(
        "mma.sync.aligned.m16n8k8.row.col.f32.tf32.tf32.f32 "
        "{%0,%1,%2,%3},{%4,%5,%6,%7},{%8,%9},{%0,%1,%2,%3};"
        : "+f"(c[0]), "+f"(c[1]), "+f"(c[2]), "+f"(c[3])
        : "r"(a0), "r"(a1), "r"(a2), "r"(a3), "r"(b0), "r"(b1));
}

// ---------------- kernel 0: combined bias+mask slabs --------------------------
// g_comb[(wm*8+h)][i][j] = table[rel[i][j]][h] + mask[wm][i][j], j=343 pad = 0
__global__ __launch_bounds__(256) void wa3d_comb_kernel(const float* __restrict__ table,
                                                        const int* __restrict__ rel,
                                                        const float* __restrict__ mask) {
    int wmh = blockIdx.x;           // 0..511
    int wm = wmh >> 3, h = wmh & 7;
    float* dst = g_comb + (long)wmh * (N_TOK * CSTR);
    int tid = threadIdx.x;
    #pragma unroll
    for (int r = 0; r < 8; r++) {
        int i = blockIdx.y * 8 + r;
        if (i >= N_TOK) break;
        for (int j = tid; j < CSTR; j += 256) {
            float v = 0.f;
            if (j < N_TOK)
                v = table[rel[i * N_TOK + j] * HEADS + h]
                  + mask[((long)wm * N_TOK + i) * N_TOK + j];
            dst[i * CSTR + j] = v;
        }
    }
}

// ---------------- tf32 mma GEMM: C(128x128) per CTA, BK=16 -------------------
// MODE 0: A = Aparam (x), epilogue scatters into g_q/g_k/g_v with q-scale.
// MODE 1: A = g_attn (device symbol referenced in device code), C+bias out.
template<int LDW, int MODE>
__global__ __launch_bounds__(256, 2) void wa3d_gemm(const float* __restrict__ Aparam,
                                                    const float* __restrict__ W,
                                                    const float* __restrict__ bias,
                                                    float* __restrict__ out) {
    __shared__ uint32_t As[2][128 * 20];
    __shared__ uint32_t Bs[2][16 * 132];

    int tid = threadIdx.x;
    int w = tid >> 5, lane = tid & 31, g = lane >> 2, t = lane & 3;
    int wm = (w & 3) * 32, wn = (w >> 2) * 64;
    int bm = blockIdx.x, bn = blockIdx.y;
    const float* Asrc = (MODE == 0) ? Aparam : (const float*)g_attn;
    const float* Ab = Asrc + (long)bm * 128 * 256;
    const float* Wb = W + bn * 128;

    float acc[2][8][4];
    #pragma unroll
    for (int mf = 0; mf < 2; mf++)
        #pragma unroll
        for (int nf = 0; nf < 8; nf++)
            #pragma unroll
            for (int e = 0; e < 4; e++) acc[mf][nf][e] = 0.f;

    float4 pa[2], pb[2];
    #pragma unroll
    for (int i = 0; i < 2; i++) {
        int id = tid + 256 * i;
        pa[i] = *(const float4*)(Ab + (id >> 2) * 256 + (id & 3) * 4);
        pb[i] = *(const float4*)(Wb + (long)(id >> 5) * LDW + (id & 31) * 4);
    }
    #pragma unroll
    for (int i = 0; i < 2; i++) {
        int id = tid + 256 * i;
        uint4 va = {f2tf(pa[i].x), f2tf(pa[i].y), f2tf(pa[i].z), f2tf(pa[i].w)};
        *(uint4*)&As[0][(id >> 2) * 20 + (id & 3) * 4] = va;
        uint4 vb = {f2tf(pb[i].x), f2tf(pb[i].y), f2tf(pb[i].z), f2tf(pb[i].w)};
        *(uint4*)&Bs[0][(id >> 5) * 132 + (id & 31) * 4] = vb;
    }
    __syncthreads();

    for (int s = 0; s < 16; s++) {
        int buf = s & 1;
        if (s < 15) {
            int k0 = (s + 1) * 16;
            #pragma unroll
            for (int i = 0; i < 2; i++) {
                int id = tid + 256 * i;
                pa[i] = *(const float4*)(Ab + (id >> 2) * 256 + k0 + (id & 3) * 4);
                pb[i] = *(const float4*)(Wb + (long)(k0 + (id >> 5)) * LDW + (id & 31) * 4);
            }
        }
        const uint32_t* Asb = As[buf];
        const uint32_t* Bsb = Bs[buf];
        #pragma unroll
        for (int kk = 0; kk < 2; kk++) {
            int k = kk * 8;
            uint32_t afr[2][4];
            #pragma unroll
            for (int mf = 0; mf < 2; mf++) {
                const uint32_t* ap = Asb + (wm + mf * 16 + g) * 20 + k + t;
                afr[mf][0] = ap[0];
                afr[mf][1] = ap[8 * 20];
                afr[mf][2] = ap[4];
                afr[mf][3] = ap[8 * 20 + 4];
            }
            #pragma unroll
            for (int nf = 0; nf < 8; nf++) {
                const uint32_t* bp = Bsb + (k + t) * 132 + wn + nf * 8 + g;
                uint32_t b0 = bp[0], b1 = bp[4 * 132];
                mma8(acc[0][nf], afr[0][0], afr[0][1], afr[0][2], afr[0][3], b0, b1);
                mma8(acc[1][nf], afr[1][0], afr[1][1], afr[1][2], afr[1][3], b0, b1);
            }
        }
        if (s < 15) {
            int nb = (s + 1) & 1;
            #pragma unroll
            for (int i = 0; i < 2; i++) {
                int id = tid + 256 * i;
                uint4 va = {f2tf(pa[i].x), f2tf(pa[i].y), f2tf(pa[i].z), f2tf(pa[i].w)};
                *(uint4*)&As[nb][(id >> 2) * 20 + (id & 3) * 4] = va;
                uint4 vb = {f2tf(pb[i].x), f2tf(pb[i].y), f2tf(pb[i].z), f2tf(pb[i].w)};
                *(uint4*)&Bs[nb][(id >> 5) * 132 + (id & 31) * 4] = vb;
            }
        }
        __syncthreads();
    }

    // ----- epilogue -----
    if (MODE == 0) {
        #pragma unroll
        for (int mf = 0; mf < 2; mf++) {
            #pragma unroll
            for (int half = 0; half < 2; half++) {
                int row = bm * 128 + wm + mf * 16 + g + half * 8;
                int bwin = row / N_TOK, n = row - bwin * N_TOK;
                #pragma unroll
                for (int nf = 0; nf < 8; nf++) {
                    #pragma unroll
                    for (int e2 = 0; e2 < 2; e2++) {
                        int c = bn * 128 + wn + nf * 8 + 2 * t + e2;
                        float v = acc[mf][nf][half * 2 + e2] + bias[c];
                        int sct = c >> 8;
                        int hh = (c >> 5) & 7;
                        int d = c & 31;
                        float* dst = (sct == 0) ? g_q : (sct == 1) ? g_k : g_v;
                        if (sct == 0) v *= QSCALE;
                        dst[((bwin * HEADS + hh) * N_TOK + n) * HD + d] = v;
                    }
                }
            }
        }
    } else {
        #pragma unroll
        for (int mf = 0; mf < 2; mf++) {
            #pragma unroll
            for (int half = 0; half < 2; half++) {
                int row = bm * 128 + wm + mf * 16 + g + half * 8;
                #pragma unroll
                for (int nf = 0; nf < 8; nf++) {
                    int c = bn * 128 + wn + nf * 8 + 2 * t;
                    float2 st;
                    st.x = acc[mf][nf][half * 2 + 0] + bias[c];
                    st.y = acc[mf][nf][half * 2 + 1] + bias[c + 1];
                    *(float2*)&out[(long)row * 256 + c] = st;
                }
            }
        }
    }
}

// ---------------- attention: tf32 mma flash-style, one CTA per (b,h) ---------
#define ATTN_SMEM_U32 (352 * 36 + 352 * 40 + 64 * 36 + 64 + 64 + 128)
#define ATTN_SMEM (ATTN_SMEM_U32 * 4)

__global__ __launch_bounds__(256, 1) void wa3d_attn_kernel() {
    extern __shared__ uint32_t smu[];
    uint32_t* ks = smu;                       // 352*36
    uint32_t* vs = ks + 352 * 36;             // 352*40
    uint32_t* qs = vs + 352 * 40;             // 64*36  (>= 2048 scratch floats)
    float* sm_m = (float*)(qs + 64 * 36);     // 128
    float* sm_s = sm_m + 128;                 // 128

    int bx = blockIdx.x;
    int h = bx & 7, b = bx >> 3;
    int tid = threadIdx.x, w = tid >> 5, lane = tid & 31;
    int g = lane >> 2, t = lane & 3;
    long base = (long)(b * HEADS + h) * (N_TOK * HD);
    const float* kb = g_k + base;
    const float* vb = g_v + base;
    const float* qb = g_q + base;
    const float* cb = g_comb + (long)((b & 63) * HEADS + h) * (N_TOK * CSTR);
    float* ob = g_attn + (long)b * (N_TOK * DIM) + h * HD;

    // stage K (tf32, stride 36) and V (tf32, stride 40), zero-padded
    for (int idx = tid; idx < 352 * 32; idx += 256) {
        int r = idx >> 5, d = idx & 31;
        float kv = (r < N_TOK) ? kb[r * HD + d] : 0.f;
        float vv = (r < N_TOK) ? vb[r * HD + d] : 0.f;
        ks[r * 36 + d] = f2tf(kv);
        vs[r * 40 + d] = f2tf(vv);
    }
    __syncthreads();

    int mi = (w & 3) * 16;         // row tile within strip
    int jhi = w >> 2;              // j-half index (0/1)
    int jh = jhi * 176;            // j-col base
    float* scratch = (float*)qs;
    int srcA = (lane & 28) | (t >> 1);

    for (int is = 0; is < 6; is++) {
        int i0 = is * 64;
        // stage Q strip (64 rows, tf32, stride 36)
        for (int idx = tid; idx < 64 * 32; idx += 256) {
            int r = idx >> 5, d = idx & 31;
            int i = i0 + r;
            float qv = (i < N_TOK) ? qb[i * HD + d] : 0.f;
            qs[r * 36 + d] = f2tf(qv);
        }
        __syncthreads();

        // ---- S = Q K^T over this warp's 16 rows x 176 cols ----
        float sacc[22][4];
        #pragma unroll
        for (int nf = 0; nf < 22; nf++)
            #pragma unroll
            for (int e = 0; e < 4; e++) sacc[nf][e] = 0.f;

        #pragma unroll
        for (int kk = 0; kk < 4; kk++) {
            int k = kk * 8;
            const uint32_t* ap = qs + (mi + g) * 36 + k + t;
            uint32_t a0 = ap[0], a1 = ap[8 * 36], a2 = ap[4], a3 = ap[8 * 36 + 4];
            #pragma unroll
            for (int nf = 0; nf < 22; nf++) {
                const uint32_t* bp = ks + (jh + nf * 8 + g) * 36 + k + t;
                mma8(sacc[nf], a0, a1, a2, a3, bp[0], bp[4]);  // b1: k+4 (dim axis)
            }
        }

        // ---- + combined(bias+mask) via aligned float2 loads ----
        int i_lo = i0 + mi + g;
        int i_hi = i_lo + 8;
        bool rlo = i_lo < N_TOK, rhi = i_hi < N_TOK;
        const float* cb0 = cb + (long)i_lo * CSTR;
        const float* cb1 = cb + (long)i_hi * CSTR;
        #pragma unroll
        for (int nf = 0; nf < 22; nf++) {
            int j0 = jh + nf * 8 + 2 * t;
            bool j0v = j0 < N_TOK;           // j0 even, so j0 <= 342 here
            bool j1v = (j0 + 1) < N_TOK;
            float2 c0 = (rlo && j0v) ? *(const float2*)&cb0[j0] : make_float2(0.f, 0.f);
            float2 c1 = (rhi && j0v) ? *(const float2*)&cb1[j0] : make_float2(0.f, 0.f);
            sacc[nf][0] = (rlo && j0v) ? sacc[nf][0] + c0.x : -1e30f;
            sacc[nf][1] = (rlo && j1v) ? sacc[nf][1] + c0.y : -1e30f;
            sacc[nf][2] = (rhi && j0v) ? sacc[nf][2] + c1.x : -1e30f;
            sacc[nf][3] = (rhi && j1v) ? sacc[nf][3] + c1.y : -1e30f;
        }

        // ---- softmax (registers + cross-warp pair exchange) ----
        float mlo = -1e30f, mhi = -1e30f;
        #pragma unroll
        for (int nf = 0; nf < 22; nf++) {
            mlo = fmaxf(mlo, fmaxf(sacc[nf][0], sacc[nf][1]));
            mhi = fmaxf(mhi, fmaxf(sacc[nf][2], sacc[nf][3]));
        }
        #pragma unroll
        for (int off = 1; off <= 2; off <<= 1) {
            mlo = fmaxf(mlo, __shfl_xor_sync(0xffffffffu, mlo, off));
            mhi = fmaxf(mhi, __shfl_xor_sync(0xffffffffu, mhi, off));
        }
        if (t == 0) {
            sm_m[jhi * 64 + mi + g] = mlo;
            sm_m[jhi * 64 + mi + 8 + g] = mhi;
        }
        __syncthreads();
        mlo = fmaxf(mlo, sm_m[(jhi ^ 1) * 64 + mi + g]);
        mhi = fmaxf(mhi, sm_m[(jhi ^ 1) * 64 + mi + 8 + g]);

        float slo = 0.f, shi = 0.f;
        #pragma unroll
        for (int nf = 0; nf < 22; nf++) {
            float e0 = __expf(sacc[nf][0] - mlo);
            float e1 = __expf(sacc[nf][1] - mlo);
            float e2 = __expf(sacc[nf][2] - mhi);
            float e3 = __expf(sacc[nf][3] - mhi);
            sacc[nf][0] = e0; sacc[nf][1] = e1; sacc[nf][2] = e2; sacc[nf][3] = e3;
            slo += e0 + e1;
            shi += e2 + e3;
        }
        #pragma unroll
        for (int off = 1; off <= 2; off <<= 1) {
            slo += __shfl_xor_sync(0xffffffffu, slo, off);
            shi += __shfl_xor_sync(0xffffffffu, shi, off);
        }
        if (t == 0) {
            sm_s[jhi * 64 + mi + g] = slo;
            sm_s[jhi * 64 + mi + 8 + g] = shi;
        }
        __syncthreads();
        slo += sm_s[(jhi ^ 1) * 64 + mi + g];
        shi += sm_s[(jhi ^ 1) * 64 + mi + 8 + g];
        float invlo = 1.f / slo, invhi = 1.f / shi;

        // ---- PV: permute S c-frags -> a-frags via shfl, mma against V ----
        float oacc[4][4];
        #pragma unroll
        for (int nv = 0; nv < 4; nv++)
            #pragma unroll
            for (int e = 0; e < 4; e++) oacc[nv][e] = 0.f;

        #pragma unroll
        for (int nf = 0; nf < 22; nf++) {
            int k = jh + nf * 8;
            uint32_t e0 = f2tf(sacc[nf][0]);
            uint32_t e1 = f2tf(sacc[nf][1]);
            uint32_t e2 = f2tf(sacc[nf][2]);
            uint32_t e3 = f2tf(sacc[nf][3]);
            uint32_t x0 = __shfl_sync(0xffffffffu, e0, srcA);
            uint32_t x1 = __shfl_sync(0xffffffffu, e1, srcA);
            uint32_t a0 = (t & 1) ? x1 : x0;
            uint32_t y0 = __shfl_sync(0xffffffffu, e0, srcA + 2);
            uint32_t y1 = __shfl_sync(0xffffffffu, e1, srcA + 2);
            uint32_t a2 = (t & 1) ? y1 : y0;
            x0 = __shfl_sync(0xffffffffu, e2, srcA);
            x1 = __shfl_sync(0xffffffffu, e3, srcA);
            uint32_t a1 = (t & 1) ? x1 : x0;
            y0 = __shfl_sync(0xffffffffu, e2, srcA + 2);
            y1 = __shfl_sync(0xffffffffu, e3, srcA + 2);
            uint32_t a3 = (t & 1) ? y1 : y0;
            const uint32_t* vp = vs + (k + t) * 40 + g;
            #pragma unroll
            for (int nv = 0; nv < 4; nv++)
                mma8(oacc[nv], a0, a1, a2, a3, vp[nv * 8], vp[4 * 40 + nv * 8]);
        }

        // ---- reduce across j-halves, scale by 1/sum, write out ----
        if (w >= 4) {
            float* sc = scratch + (w - 4) * 512;
            #pragma unroll
            for (int nv = 0; nv < 4; nv++)
                #pragma unroll
                for (int e = 0; e < 4; e++)
                    sc[(nv * 4 + e) * 32 + lane] = oacc[nv][e];
        }
        __syncthreads();
        if (w < 4) {
            float* sc = scratch + w * 512;
            #pragma unroll
            for (int nv = 0; nv < 4; nv++)
                #pragma unroll
                for (int e = 0; e < 4; e++)
                    oacc[nv][e] += sc[(nv * 4 + e) * 32 + lane];
            int ir0 = i0 + mi + g;
            int ir1 = ir0 + 8;
            #pragma unroll
            for (int nv = 0; nv < 4; nv++) {
                int col = nv * 8 + 2 * t;
                if (ir0 < N_TOK) {
                    float2 v;
                    v.x = oacc[nv][0] * invlo;
                    v.y = oacc[nv][1] * invlo;
                    *(float2*)&ob[(long)ir0 * DIM + col] = v;
                }
                if (ir1 < N_TOK) {
                    float2 v;
                    v.x = oacc[nv][2] * invhi;
                    v.y = oacc[nv][3] * invhi;
                    *(float2*)&ob[(long)ir1 * DIM + col] = v;
                }
            }
        }
        __syncthreads();   // protect qs (scratch) + sm arrays before next strip
    }
}

// ------------------------------ launch ----------------------------------------
extern "C" void kernel_launch(void* const* d_in, const int* in_sizes, int n_in,
                              void* d_out, int out_size) {
    const float* x      = (const float*)d_in[0];
    const float* mask   = (const float*)d_in[1];
    const float* qkv_w  = (const float*)d_in[2];
    const float* qkv_b  = (const float*)d_in[3];
    const float* proj_w = (const float*)d_in[4];
    const float* proj_b = (const float*)d_in[5];
    const float* rpb    = (const float*)d_in[6];
    const int*   rel    = (const int*)d_in[7];
    float* out = (float*)d_out;

    cudaFuncSetAttribute(wa3d_attn_kernel,
                         cudaFuncAttributeMaxDynamicSharedMemorySize, ATTN_SMEM);

    wa3d_comb_kernel<<<dim3(64 * HEADS, (N_TOK + 7) / 8), 256>>>(rpb, rel, mask);
    wa3d_gemm<768, 0><<<dim3(ROWS_TOT / 128, 6), 256>>>(x, qkv_w, qkv_b, nullptr);
    wa3d_attn_kernel<<<BWIN * HEADS, 256, ATTN_SMEM>>>();
    wa3d_gemm<256, 1><<<dim3(ROWS_TOT / 128, 2), 256>>>(nullptr, proj_w, proj_b, out);
}